// round 5
// baseline (speedup 1.0000x reference)
#include <cuda_runtime.h>
#include <math.h>

// Shapes (fixed by the problem)
#define BB 2
#define SS 128
#define DD 64
#define FF 256
#define DD2 (DD*DD)
#define NFS 2           // f-splits in k_main
#define NG  (NFS*SS)    // 256 split-K groups per batch
#define KC 32           // f-chunk in main kernel
#define WROW 82         // u64 pitch of one k-row in Wd (8-groups at 10-u64 pitch + 2 pad)

typedef unsigned long long u64;

// -------- scratch (device globals: sanctioned, no runtime alloc) --------
__device__ float g_A[BB*SS*FF];              // A[b,i,f]
__device__ float g_C[BB*SS*FF];              // C[b,j,f] (includes gb1)
__device__ float g_W[BB*SS*FF*DD];           // W[b,j,f,e]  16 MB
__device__ float g_Pagg[BB*NG*SS*DD];        // partial agg per group, 16.8 MB
__device__ float g_bias2[BB*DD];             // sum_d gb2[d,e]*Sphi[b,d]

// -------- packed fp32x2 helpers (Blackwell PTX-only FFMA2) --------
__device__ __forceinline__ u64 dup2(float x){
    u64 r; asm("mov.b64 %0, {%1, %1};" : "=l"(r) : "f"(x)); return r;
}
__device__ __forceinline__ u64 fma2(u64 a, u64 b, u64 c){
    u64 d; asm("fma.rn.f32x2 %0, %1, %2, %3;" : "=l"(d) : "l"(a), "l"(b), "l"(c)); return d;
}
__device__ __forceinline__ u64 add2(u64 a, u64 b){
    u64 d; asm("add.rn.f32x2 %0, %1, %2;" : "=l"(d) : "l"(a), "l"(b)); return d;
}
__device__ __forceinline__ float2 unpk(u64 a){
    float2 r; asm("mov.b64 {%0, %1}, %2;" : "=f"(r.x), "=f"(r.y) : "l"(a)); return r;
}
union F4U { float4 f4; ulonglong2 u2; };

__device__ __forceinline__ float gelu_exact(float x){
    return 0.5f * x * (1.0f + erff(x * 0.7071067811865476f));
}

// fast tanh-gelu: 0.5x(1+tanh(0.79788456(x+0.044715x^3))), tanh.approx = 1 MUFU
__device__ __forceinline__ float gelu_fast(float x){
    float x2 = x * x;
    float inner = x * fmaf(0.035677408136f, x2, 0.797884560803f);
    float th;
    asm("tanh.approx.f32 %0, %1;" : "=f"(th) : "f"(inner));
    float hx = 0.5f * x;
    return fmaf(hx, th, hx);
}

// ==================== k_w: W + fused prep(A,C) + bias2 ====================
// grid (256 f, 2 b), 256 threads; thread owns 8 rows x 4 e (register blocked).
// Fused extras: block f<128 also computes A/C row (b, i=f); block f==128 bias2[b].
__global__ void __launch_bounds__(256) k_w(const float* __restrict__ q,
                                           const float* __restrict__ gw2,
                                           const float* __restrict__ gw1,
                                           const float* __restrict__ gb1,
                                           const float* __restrict__ gb2){
    __shared__ float phiT[DD][SS];              // 32 KB, [d][r]
    __shared__ __align__(16) float g2[DD*DD];   // 16 KB, [d][e]
    __shared__ float sph[DD];
    int f = blockIdx.x, b = blockIdx.y;
    int t = threadIdx.x;
    {
        const float4* src = (const float4*)(gw2 + (size_t)f*DD2);
        float4* dst = (float4*)g2;
        #pragma unroll
        for (int p = 0; p < 4; p++) dst[p*256 + t] = src[p*256 + t];
    }
    {
        int r = t & 127, half = t >> 7;
        #pragma unroll
        for (int d4 = 0; d4 < 8; d4++){
            int d0 = half*32 + d4*4;
            float4 v = *(const float4*)(q + ((size_t)b*SS + r)*DD + d0);
            phiT[d0  ][r] = v.x; phiT[d0+1][r] = v.y;
            phiT[d0+2][r] = v.z; phiT[d0+3][r] = v.w;
        }
    }
    __syncthreads();
    int e0 = (t >> 4) * 4;
    int r0 = (t & 15) * 8;
    u64 acc[4][4];
    #pragma unroll
    for (int x = 0; x < 4; x++)
        #pragma unroll
        for (int y = 0; y < 4; y++) acc[x][y] = 0ULL;
    #pragma unroll 8
    for (int d = 0; d < DD; d++){
        F4U p0, p1;
        p0.f4 = *(const float4*)&phiT[d][r0];
        p1.f4 = *(const float4*)&phiT[d][r0 + 4];
        float4 w = *(const float4*)&g2[d*DD + e0];
        u64 w0 = dup2(w.x), w1 = dup2(w.y), w2 = dup2(w.z), w3 = dup2(w.w);
        u64 hp0 = p0.u2.x, hp1 = p0.u2.y, hp2 = p1.u2.x, hp3 = p1.u2.y;
        acc[0][0]=fma2(hp0,w0,acc[0][0]); acc[0][1]=fma2(hp1,w0,acc[0][1]);
        acc[0][2]=fma2(hp2,w0,acc[0][2]); acc[0][3]=fma2(hp3,w0,acc[0][3]);
        acc[1][0]=fma2(hp0,w1,acc[1][0]); acc[1][1]=fma2(hp1,w1,acc[1][1]);
        acc[1][2]=fma2(hp2,w1,acc[1][2]); acc[1][3]=fma2(hp3,w1,acc[1][3]);
        acc[2][0]=fma2(hp0,w2,acc[2][0]); acc[2][1]=fma2(hp1,w2,acc[2][1]);
        acc[2][2]=fma2(hp2,w2,acc[2][2]); acc[2][3]=fma2(hp3,w2,acc[2][3]);
        acc[3][0]=fma2(hp0,w3,acc[3][0]); acc[3][1]=fma2(hp1,w3,acc[3][1]);
        acc[3][2]=fma2(hp2,w3,acc[3][2]); acc[3][3]=fma2(hp3,w3,acc[3][3]);
    }
    #pragma unroll
    for (int rp = 0; rp < 4; rp++){
        float2 v0 = unpk(acc[0][rp]), v1 = unpk(acc[1][rp]);
        float2 v2 = unpk(acc[2][rp]), v3 = unpk(acc[3][rp]);
        int r = r0 + rp*2;
        *(float4*)&g_W[(((size_t)b*SS + r  )*FF + f)*DD + e0] = make_float4(v0.x, v1.x, v2.x, v3.x);
        *(float4*)&g_W[(((size_t)b*SS + r+1)*FF + f)*DD + e0] = make_float4(v0.y, v1.y, v2.y, v3.y);
    }
    // ---- fused prep role: A/C row (b, i=f) for blocks f < 128 ----
    if (f < SS){
        float a = 0.f, c = gb1[t];
        #pragma unroll
        for (int d = 0; d < DD; d++){
            float p = phiT[d][f];               // broadcast
            a = fmaf(p, gw1[d*FF + t], a);
            c = fmaf(p, gw1[(DD+d)*FF + t], c);
        }
        int bi = b*SS + f;
        g_A[bi*FF + t] = a;
        g_C[bi*FF + t] = c;
    }
    // ---- fused bias2 role for block f == 128 ----
    if (f == SS){
        if (t < DD){
            float s = 0.f;
            #pragma unroll 8
            for (int r = 0; r < SS; r++) s += phiT[t][r];
            sph[t] = s;
        }
        __syncthreads();
        if (t < DD){
            float ab = 0.f;
            #pragma unroll
            for (int d = 0; d < DD; d++) ab = fmaf(gb2[d*DD + t], sph[d], ab);
            g_bias2[b*DD + t] = ab;
        }
    }
}

// ==================== k_main: split-K GEMM with fused gelu ====================
// grid (128 j, 2 fs, 2 b), 128 threads; thread owns 8 i x 8 e.
// Wd holds the W chunk pre-duplicated (u64), conflict-free padded layout:
//   Wd[k*WROW + (e>>3)*10 + (e&7)]
__global__ void __launch_bounds__(128) k_main(){
    __shared__ __align__(16) float Hs[KC*132];   // H[k][i], padded row 132 (16.9 KB)
    __shared__ __align__(16) u64   Wd[KC*WROW];  // 21 KB
    int j = blockIdx.x, fs = blockIdx.y, b = blockIdx.z;
    int t  = threadIdx.x;
    int m8 = t & 7;                               // e-group: e0 = m8*8
    int i0 = (t >> 3) * 8;
    int kk = t & 31;
    int quar = t >> 5;                            // 0..3
    u64 acc[8][4];                                // [e][i-pair]
    #pragma unroll
    for (int x = 0; x < 8; x++)
        #pragma unroll
        for (int y = 0; y < 4; y++) acc[x][y] = 0ULL;

    const float* Arow = g_A + (size_t)b*SS*FF + fs*(FF/NFS);
    const float* Crow = g_C + ((size_t)b*SS + j)*FF + fs*(FF/NFS);
    const float* Wrow = g_W + ((size_t)b*SS + j)*FF*DD + (size_t)fs*(FF/NFS)*DD;

    // thread's fill mapping: 16 consecutive floats of the 2048-float chunk
    int fk = t >> 2;                              // k-row 0..31
    int fe = (t & 3) * 16;                        // e-start

    for (int c = 0; c < (FF/NFS)/KC; c++){        // 4 chunks
        int f0 = c*KC;
        __syncthreads();                          // previous chunk consumed
        // fill W chunk pre-duplicated
        {
            const float4* wsrc = (const float4*)(Wrow + f0*DD);
            #pragma unroll
            for (int qd = 0; qd < 4; qd++){
                float4 w = wsrc[t*4 + qd];
                int e = fe + qd*4;
                int off = fk*WROW + (e>>3)*10 + (e&7);
                ulonglong2 v;
                v.x = dup2(w.x); v.y = dup2(w.y);
                *(ulonglong2*)&Wd[off] = v;
                v.x = dup2(w.z); v.y = dup2(w.w);
                *(ulonglong2*)&Wd[off + 2] = v;
            }
        }
        // fill H chunk: thread owns row kk, 32 i's, vector STS.128 (conflict-free)
        {
            float cv = Crow[f0 + kk];
            #pragma unroll
            for (int m = 0; m < 8; m++){
                int ib = quar*32 + m*4;
                float4 hv;
                hv.x = gelu_fast(Arow[(ib+0)*FF + f0 + kk] + cv);
                hv.y = gelu_fast(Arow[(ib+1)*FF + f0 + kk] + cv);
                hv.z = gelu_fast(Arow[(ib+2)*FF + f0 + kk] + cv);
                hv.w = gelu_fast(Arow[(ib+3)*FF + f0 + kk] + cv);
                *(float4*)&Hs[kk*132 + ib] = hv;
            }
        }
        __syncthreads();
        // FMA loop: 6 LDS.128 + 32 fma2 per k
        #pragma unroll 2
        for (int k = 0; k < KC; k++){
            F4U h0, h1;
            h0.f4 = *(const float4*)&Hs[k*132 + i0];
            h1.f4 = *(const float4*)&Hs[k*132 + i0 + 4];
            const ulonglong2* wp = (const ulonglong2*)&Wd[k*WROW + m8*10];
            ulonglong2 wa = wp[0], wb = wp[1], wc = wp[2], we = wp[3];
            u64 hp[4] = {h0.u2.x, h0.u2.y, h1.u2.x, h1.u2.y};
            u64 wd8[8] = {wa.x, wa.y, wb.x, wb.y, wc.x, wc.y, we.x, we.y};
            #pragma unroll
            for (int e = 0; e < 8; e++)
                #pragma unroll
                for (int ip = 0; ip < 4; ip++)
                    acc[e][ip] = fma2(hp[ip], wd8[e], acc[e][ip]);
        }
    }
    // write partials, group G = fs*SS + j
    int e0 = m8*8;
    float* outp = g_Pagg + (((size_t)b*NG + fs*SS + j)*SS)*DD;
    #pragma unroll
    for (int ip = 0; ip < 4; ip++){
        float2 v[8];
        #pragma unroll
        for (int e = 0; e < 8; e++) v[e] = unpk(acc[e][ip]);
        int ia = i0 + ip*2;
        *(float4*)&outp[(ia  )*DD + e0    ] = make_float4(v[0].x, v[1].x, v[2].x, v[3].x);
        *(float4*)&outp[(ia  )*DD + e0 + 4] = make_float4(v[4].x, v[5].x, v[6].x, v[7].x);
        *(float4*)&outp[(ia+1)*DD + e0    ] = make_float4(v[0].y, v[1].y, v[2].y, v[3].y);
        *(float4*)&outp[(ia+1)*DD + e0 + 4] = make_float4(v[4].y, v[5].y, v[6].y, v[7].y);
    }
}

// ==================== k_epi: vectorized reduce + LN1 + MLP + LN2 ====================
// grid 256 (b*S rows), 256 threads
__global__ void __launch_bounds__(256) k_epi(const float* __restrict__ q,
                                             const float* __restrict__ mw1,
                                             const float* __restrict__ mb1,
                                             const float* __restrict__ mw2,
                                             const float* __restrict__ mb2,
                                             const float* __restrict__ l1g,
                                             const float* __restrict__ l1b,
                                             const float* __restrict__ l2g,
                                             const float* __restrict__ l2b,
                                             float* __restrict__ out){
    __shared__ float ps2[16][68];
    __shared__ float xs[DD];
    __shared__ float ys[DD];
    __shared__ float h2[FF];
    __shared__ float stats[2];
    int bi = blockIdx.x;
    int b = bi >> 7, i = bi & 127;
    int t = threadIdx.x;
    // ---- vectorized deterministic reduce: thread (p, slot) sums 16 groups x float4
    {
        int slot = t & 15, p = t >> 4;
        int e0 = slot * 4;
        u64 s01 = 0ULL, s23 = 0ULL;
        const float* base = g_Pagg + (((size_t)b*NG + p*16)*SS + i)*DD + e0;
        #pragma unroll
        for (int g = 0; g < 16; g++){
            F4U v; v.f4 = *(const float4*)(base + (size_t)g*SS*DD);
            s01 = add2(s01, v.u2.x);
            s23 = add2(s23, v.u2.y);
        }
        float2 a01 = unpk(s01), a23 = unpk(s23);
        *(float4*)&ps2[p][e0] = make_float4(a01.x, a01.y, a23.x, a23.y);
    }
    __syncthreads();
    if (t < DD){
        float agg = 0.f;
        #pragma unroll
        for (int p = 0; p < 16; p++) agg += ps2[p][t];
        xs[t] = q[bi*DD + t] + agg + g_bias2[b*DD + t];
    }
    __syncthreads();
    // LN1
    if (t < 32){
        float v = xs[t] + xs[t+32];
        #pragma unroll
        for (int o = 16; o > 0; o >>= 1) v += __shfl_xor_sync(0xffffffffu, v, o);
        float mu = v * (1.0f/64.0f);
        float d0 = xs[t]-mu, d1 = xs[t+32]-mu;
        float w = d0*d0 + d1*d1;
        #pragma unroll
        for (int o = 16; o > 0; o >>= 1) w += __shfl_xor_sync(0xffffffffu, w, o);
        if (t == 0){ stats[0] = mu; stats[1] = rsqrtf(w*(1.0f/64.0f) + 1e-5f); }
    }
    __syncthreads();
    if (t < DD) xs[t] = (xs[t]-stats[0])*stats[1]*l1g[t] + l1b[t];
    __syncthreads();
    // MLP fc1 + exact gelu (thread = f)
    {
        float h = mb1[t];
        #pragma unroll
        for (int d = 0; d < DD; d++) h = fmaf(xs[d], mw1[d*FF + t], h);
        h2[t] = gelu_exact(h);
    }
    __syncthreads();
    // fc2 parallel over 256 threads: quarter-of-f per partition, deterministic combine
    {
        int e = t & 63, p4 = t >> 6;
        float o = 0.f;
        #pragma unroll 8
        for (int f2 = 0; f2 < FF/4; f2++){
            int fi = p4*(FF/4) + f2;
            o = fmaf(h2[fi], mw2[fi*DD + e], o);
        }
        ps2[p4][e] = o;
    }
    __syncthreads();
    if (t < DD)
        ys[t] = xs[t] + mb2[t] + ((ps2[0][t] + ps2[1][t]) + (ps2[2][t] + ps2[3][t]));
    __syncthreads();
    // LN2
    if (t < 32){
        float v = ys[t] + ys[t+32];
        #pragma unroll
        for (int o = 16; o > 0; o >>= 1) v += __shfl_xor_sync(0xffffffffu, v, o);
        float mu = v * (1.0f/64.0f);
        float d0 = ys[t]-mu, d1 = ys[t+32]-mu;
        float w = d0*d0 + d1*d1;
        #pragma unroll
        for (int o = 16; o > 0; o >>= 1) w += __shfl_xor_sync(0xffffffffu, w, o);
        if (t == 0){ stats[0] = mu; stats[1] = rsqrtf(w*(1.0f/64.0f) + 1e-5f); }
    }
    __syncthreads();
    if (t < DD)
        out[bi*DD + t] = (ys[t]-stats[0])*stats[1]*l2g[t] + l2b[t];
}

extern "C" void kernel_launch(void* const* d_in, const int* in_sizes, int n_in,
                              void* d_out, int out_size){
    const float* q   = (const float*)d_in[0];
    const float* gw1 = (const float*)d_in[1];
    const float* gb1 = (const float*)d_in[2];
    const float* gw2 = (const float*)d_in[3];
    const float* gb2 = (const float*)d_in[4];
    const float* mw1 = (const float*)d_in[5];
    const float* mb1 = (const float*)d_in[6];
    const float* mw2 = (const float*)d_in[7];
    const float* mb2 = (const float*)d_in[8];
    const float* l1g = (const float*)d_in[9];
    const float* l1b = (const float*)d_in[10];
    const float* l2g = (const float*)d_in[11];
    const float* l2b = (const float*)d_in[12];
    float* out = (float*)d_out;

    k_w<<<dim3(FF, BB), 256>>>(q, gw2, gw1, gb1, gb2);
    k_main<<<dim3(SS, NFS, BB), 128>>>();
    k_epi<<<BB*SS, 256>>>(q, mw1, mb1, mw2, mb2, l1g, l1b, l2g, l2b, out);
}

// round 6
// speedup vs baseline: 1.0945x; 1.0945x over previous
#include <cuda_runtime.h>
#include <math.h>

// Shapes (fixed by the problem)
#define BB 2
#define SS 128
#define DD 64
#define FF 256
#define DD2 (DD*DD)
#define NFS 2           // f-splits in k_main
#define NG  (NFS*SS)    // 256 split-K groups per batch
#define KC 32           // f-chunk in main kernel
#define WROW 82         // u64 pitch of one k-row in Wd (8-groups at 10-u64 pitch + 2 pad)

typedef unsigned long long u64;

// -------- scratch (device globals: sanctioned, no runtime alloc) --------
__device__ float g_A[BB*SS*FF];              // A[b,i,f]
__device__ float g_C[BB*SS*FF];              // C[b,j,f] (includes gb1)
__device__ float g_W[BB*SS*FF*DD];           // W[b,j,f,e]  16 MB
__device__ float g_Pagg[BB*NG*SS*DD];        // partial agg per group, 16.8 MB
__device__ float g_bias2[BB*DD];             // sum_d gb2[d,e]*Sphi[b,d]

// -------- packed fp32x2 helpers (Blackwell PTX-only FFMA2) --------
__device__ __forceinline__ u64 dup2(float x){
    u64 r; asm("mov.b64 %0, {%1, %1};" : "=l"(r) : "f"(x)); return r;
}
__device__ __forceinline__ u64 fma2(u64 a, u64 b, u64 c){
    u64 d; asm("fma.rn.f32x2 %0, %1, %2, %3;" : "=l"(d) : "l"(a), "l"(b), "l"(c)); return d;
}
__device__ __forceinline__ u64 add2(u64 a, u64 b){
    u64 d; asm("add.rn.f32x2 %0, %1, %2;" : "=l"(d) : "l"(a), "l"(b)); return d;
}
__device__ __forceinline__ float2 unpk(u64 a){
    float2 r; asm("mov.b64 {%0, %1}, %2;" : "=f"(r.x), "=f"(r.y) : "l"(a)); return r;
}
union F4U { float4 f4; ulonglong2 u2; };

__device__ __forceinline__ float gelu_exact(float x){
    return 0.5f * x * (1.0f + erff(x * 0.7071067811865476f));
}

// fast tanh-gelu: 0.5x(1+tanh(0.79788456(x+0.044715x^3))), tanh.approx = 1 MUFU
__device__ __forceinline__ float gelu_fast(float x){
    float x2 = x * x;
    float inner = x * fmaf(0.035677408136f, x2, 0.797884560803f);
    float th;
    asm("tanh.approx.f32 %0, %1;" : "=f"(th) : "f"(inner));
    float hx = 0.5f * x;
    return fmaf(hx, th, hx);
}

// ==================== k_pre: fused prep (A,C) + sphi + bias2 ====================
// grid 257: blocks 0..255 compute A/C row; block 256 computes Sphi + bias2.
__global__ void __launch_bounds__(256) k_pre(const float* __restrict__ q,
                                             const float* __restrict__ gw1,
                                             const float* __restrict__ gb1,
                                             const float* __restrict__ gb2){
    __shared__ float sm[2][DD];
    int bid = blockIdx.x;
    int t = threadIdx.x;
    if (bid < BB*SS){
        int bi = bid, f = t;
        if (f < DD) sm[0][f] = q[bi*DD + f];
        __syncthreads();
        float a = 0.f, c = gb1[f];
        #pragma unroll
        for (int d = 0; d < DD; d++){
            float p = sm[0][d];
            a = fmaf(p, gw1[d*FF + f], a);
            c = fmaf(p, gw1[(DD+d)*FF + f], c);
        }
        g_A[bi*FF + f] = a;
        g_C[bi*FF + f] = c;
    } else {
        if (t < 128){
            int b = t >> 6, d = t & 63;
            float s = 0.f;
            #pragma unroll 8
            for (int j = 0; j < SS; j++) s += q[(b*SS + j)*DD + d];
            sm[b][d] = s;
        }
        __syncthreads();
        if (t < 128){
            int b = t >> 6, e = t & 63;
            float ab = 0.f;
            #pragma unroll
            for (int d = 0; d < DD; d++) ab = fmaf(gb2[d*DD + e], sm[b][d], ab);
            g_bias2[t] = ab;
        }
    }
}

// ==================== k_w: W[b,j,f,e] = sum_d phi[b,j,d]*gw2[f,d*64+e] ====================
// grid (256 f, 2 b), 128 threads; thread owns 8 rows x 8 e (register blocked).
__global__ void __launch_bounds__(128) k_w(const float* __restrict__ q,
                                           const float* __restrict__ gw2){
    __shared__ float phiT[DD][SS];              // 32 KB, [d][r]
    __shared__ __align__(16) float g2[DD*DD];   // 16 KB, [d][e]
    int f = blockIdx.x, b = blockIdx.y;
    int t = threadIdx.x;
    // fill g2 (gw2 row f): 4096 floats / 128 thr = 8 float4 each... 1024 f4 total
    {
        const float4* src = (const float4*)(gw2 + (size_t)f*DD2);
        float4* dst = (float4*)g2;
        #pragma unroll
        for (int p = 0; p < 8; p++) dst[p*128 + t] = src[p*128 + t];
    }
    // fill phiT transposed: thread t = row r; lanes write consecutive r -> conflict-free
    {
        const float4* qp = (const float4*)(q + ((size_t)b*SS + t)*DD);
        #pragma unroll
        for (int d4 = 0; d4 < 16; d4++){
            float4 v = qp[d4];
            int d0 = d4*4;
            phiT[d0  ][t] = v.x; phiT[d0+1][t] = v.y;
            phiT[d0+2][t] = v.z; phiT[d0+3][t] = v.w;
        }
    }
    __syncthreads();
    int e0 = (t & 7) * 8;
    int r0 = (t >> 3) * 8;
    u64 acc[8][4];                               // [e][r-pair]
    #pragma unroll
    for (int x = 0; x < 8; x++)
        #pragma unroll
        for (int y = 0; y < 4; y++) acc[x][y] = 0ULL;
    #pragma unroll 4
    for (int d = 0; d < DD; d++){
        F4U p0, p1;
        p0.f4 = *(const float4*)&phiT[d][r0];
        p1.f4 = *(const float4*)&phiT[d][r0 + 4];
        float4 wa = *(const float4*)&g2[d*DD + e0];
        float4 wb = *(const float4*)&g2[d*DD + e0 + 4];
        u64 hp[4] = {p0.u2.x, p0.u2.y, p1.u2.x, p1.u2.y};
        u64 wd8[8] = {dup2(wa.x), dup2(wa.y), dup2(wa.z), dup2(wa.w),
                      dup2(wb.x), dup2(wb.y), dup2(wb.z), dup2(wb.w)};
        #pragma unroll
        for (int e = 0; e < 8; e++)
            #pragma unroll
            for (int ip = 0; ip < 4; ip++)
                acc[e][ip] = fma2(hp[ip], wd8[e], acc[e][ip]);
    }
    // store: rows r0..r0+7 (j within b), cols e0..e0+7
    #pragma unroll
    for (int rp = 0; rp < 4; rp++){
        float2 v[8];
        #pragma unroll
        for (int e = 0; e < 8; e++) v[e] = unpk(acc[e][rp]);
        int r = r0 + rp*2;
        float* o0 = &g_W[(((size_t)b*SS + r  )*FF + f)*DD + e0];
        float* o1 = &g_W[(((size_t)b*SS + r+1)*FF + f)*DD + e0];
        *(float4*)(o0    ) = make_float4(v[0].x, v[1].x, v[2].x, v[3].x);
        *(float4*)(o0 + 4) = make_float4(v[4].x, v[5].x, v[6].x, v[7].x);
        *(float4*)(o1    ) = make_float4(v[0].y, v[1].y, v[2].y, v[3].y);
        *(float4*)(o1 + 4) = make_float4(v[4].y, v[5].y, v[6].y, v[7].y);
    }
}

// ==================== k_main: split-K GEMM with fused gelu ====================
// grid (128 j, 2 fs, 2 b), 128 threads; thread owns 8 i x 8 e.
// Wd holds the W chunk pre-duplicated (u64), conflict-free padded layout:
//   Wd[k*WROW + (e>>3)*10 + (e&7)]
__global__ void __launch_bounds__(128) k_main(){
    __shared__ __align__(16) float Hs[KC*132];   // H[k][i], padded row 132 (16.9 KB)
    __shared__ __align__(16) u64   Wd[KC*WROW];  // 21 KB
    int j = blockIdx.x, fs = blockIdx.y, b = blockIdx.z;
    int t  = threadIdx.x;
    int m8 = t & 7;                               // e-group: e0 = m8*8
    int i0 = (t >> 3) * 8;
    int kk = t & 31;
    int quar = t >> 5;                            // 0..3
    u64 acc[8][4];                                // [e][i-pair]
    #pragma unroll
    for (int x = 0; x < 8; x++)
        #pragma unroll
        for (int y = 0; y < 4; y++) acc[x][y] = 0ULL;

    const float* Arow = g_A + (size_t)b*SS*FF + fs*(FF/NFS);
    const float* Crow = g_C + ((size_t)b*SS + j)*FF + fs*(FF/NFS);
    const float* Wrow = g_W + ((size_t)b*SS + j)*FF*DD + (size_t)fs*(FF/NFS)*DD;

    int fk = t >> 2;                              // k-row 0..31
    int fe = (t & 3) * 16;                        // e-start

    for (int c = 0; c < (FF/NFS)/KC; c++){        // 4 chunks
        int f0 = c*KC;
        __syncthreads();                          // previous chunk consumed
        // fill W chunk pre-duplicated
        {
            const float4* wsrc = (const float4*)(Wrow + f0*DD);
            #pragma unroll
            for (int qd = 0; qd < 4; qd++){
                float4 w = wsrc[t*4 + qd];
                int e = fe + qd*4;
                int off = fk*WROW + (e>>3)*10 + (e&7);
                ulonglong2 v;
                v.x = dup2(w.x); v.y = dup2(w.y);
                *(ulonglong2*)&Wd[off] = v;
                v.x = dup2(w.z); v.y = dup2(w.w);
                *(ulonglong2*)&Wd[off + 2] = v;
            }
        }
        // fill H chunk: thread owns row kk, 32 i's, vector STS.128 (conflict-free)
        {
            float cv = Crow[f0 + kk];
            #pragma unroll
            for (int m = 0; m < 8; m++){
                int ib = quar*32 + m*4;
                float4 hv;
                hv.x = gelu_fast(Arow[(ib+0)*FF + f0 + kk] + cv);
                hv.y = gelu_fast(Arow[(ib+1)*FF + f0 + kk] + cv);
                hv.z = gelu_fast(Arow[(ib+2)*FF + f0 + kk] + cv);
                hv.w = gelu_fast(Arow[(ib+3)*FF + f0 + kk] + cv);
                *(float4*)&Hs[kk*132 + ib] = hv;
            }
        }
        __syncthreads();
        // FMA loop: 6 LDS.128 + 32 fma2 per k
        #pragma unroll 2
        for (int k = 0; k < KC; k++){
            F4U h0, h1;
            h0.f4 = *(const float4*)&Hs[k*132 + i0];
            h1.f4 = *(const float4*)&Hs[k*132 + i0 + 4];
            const ulonglong2* wp = (const ulonglong2*)&Wd[k*WROW + m8*10];
            ulonglong2 wa = wp[0], wb = wp[1], wc = wp[2], we = wp[3];
            u64 hp[4] = {h0.u2.x, h0.u2.y, h1.u2.x, h1.u2.y};
            u64 wd8[8] = {wa.x, wa.y, wb.x, wb.y, wc.x, wc.y, we.x, we.y};
            #pragma unroll
            for (int e = 0; e < 8; e++)
                #pragma unroll
                for (int ip = 0; ip < 4; ip++)
                    acc[e][ip] = fma2(hp[ip], wd8[e], acc[e][ip]);
        }
    }
    // write partials, group G = fs*SS + j
    int e0 = m8*8;
    float* outp = g_Pagg + (((size_t)b*NG + fs*SS + j)*SS)*DD;
    #pragma unroll
    for (int ip = 0; ip < 4; ip++){
        float2 v[8];
        #pragma unroll
        for (int e = 0; e < 8; e++) v[e] = unpk(acc[e][ip]);
        int ia = i0 + ip*2;
        *(float4*)&outp[(ia  )*DD + e0    ] = make_float4(v[0].x, v[1].x, v[2].x, v[3].x);
        *(float4*)&outp[(ia  )*DD + e0 + 4] = make_float4(v[4].x, v[5].x, v[6].x, v[7].x);
        *(float4*)&outp[(ia+1)*DD + e0    ] = make_float4(v[0].y, v[1].y, v[2].y, v[3].y);
        *(float4*)&outp[(ia+1)*DD + e0 + 4] = make_float4(v[4].y, v[5].y, v[6].y, v[7].y);
    }
}

// ==================== k_epi: vectorized reduce + LN1 + MLP + LN2 ====================
// grid 256 (b*S rows), 256 threads
__global__ void __launch_bounds__(256) k_epi(const float* __restrict__ q,
                                             const float* __restrict__ mw1,
                                             const float* __restrict__ mb1,
                                             const float* __restrict__ mw2,
                                             const float* __restrict__ mb2,
                                             const float* __restrict__ l1g,
                                             const float* __restrict__ l1b,
                                             const float* __restrict__ l2g,
                                             const float* __restrict__ l2b,
                                             float* __restrict__ out){
    __shared__ float ps2[16][68];
    __shared__ float xs[DD];
    __shared__ float ys[DD];
    __shared__ float h2[FF];
    __shared__ float stats[2];
    int bi = blockIdx.x;
    int b = bi >> 7, i = bi & 127;
    int t = threadIdx.x;
    // ---- vectorized deterministic reduce: thread (p, slot) sums 16 groups x float4
    {
        int slot = t & 15, p = t >> 4;
        int e0 = slot * 4;
        u64 s01 = 0ULL, s23 = 0ULL;
        const float* base = g_Pagg + (((size_t)b*NG + p*16)*SS + i)*DD + e0;
        #pragma unroll
        for (int g = 0; g < 16; g++){
            F4U v; v.f4 = *(const float4*)(base + (size_t)g*SS*DD);
            s01 = add2(s01, v.u2.x);
            s23 = add2(s23, v.u2.y);
        }
        float2 a01 = unpk(s01), a23 = unpk(s23);
        *(float4*)&ps2[p][e0] = make_float4(a01.x, a01.y, a23.x, a23.y);
    }
    __syncthreads();
    if (t < DD){
        float agg = 0.f;
        #pragma unroll
        for (int p = 0; p < 16; p++) agg += ps2[p][t];
        xs[t] = q[bi*DD + t] + agg + g_bias2[b*DD + t];
    }
    __syncthreads();
    // LN1
    if (t < 32){
        float v = xs[t] + xs[t+32];
        #pragma unroll
        for (int o = 16; o > 0; o >>= 1) v += __shfl_xor_sync(0xffffffffu, v, o);
        float mu = v * (1.0f/64.0f);
        float d0 = xs[t]-mu, d1 = xs[t+32]-mu;
        float w = d0*d0 + d1*d1;
        #pragma unroll
        for (int o = 16; o > 0; o >>= 1) w += __shfl_xor_sync(0xffffffffu, w, o);
        if (t == 0){ stats[0] = mu; stats[1] = rsqrtf(w*(1.0f/64.0f) + 1e-5f); }
    }
    __syncthreads();
    if (t < DD) xs[t] = (xs[t]-stats[0])*stats[1]*l1g[t] + l1b[t];
    __syncthreads();
    // MLP fc1 + exact gelu (thread = f)
    {
        float h = mb1[t];
        #pragma unroll
        for (int d = 0; d < DD; d++) h = fmaf(xs[d], mw1[d*FF + t], h);
        h2[t] = gelu_exact(h);
    }
    __syncthreads();
    // fc2 parallel over 256 threads: quarter-of-f per partition, deterministic combine
    {
        int e = t & 63, p4 = t >> 6;
        float o = 0.f;
        #pragma unroll 8
        for (int f2 = 0; f2 < FF/4; f2++){
            int fi = p4*(FF/4) + f2;
            o = fmaf(h2[fi], mw2[fi*DD + e], o);
        }
        ps2[p4][e] = o;
    }
    __syncthreads();
    if (t < DD)
        ys[t] = xs[t] + mb2[t] + ((ps2[0][t] + ps2[1][t]) + (ps2[2][t] + ps2[3][t]));
    __syncthreads();
    // LN2
    if (t < 32){
        float v = ys[t] + ys[t+32];
        #pragma unroll
        for (int o = 16; o > 0; o >>= 1) v += __shfl_xor_sync(0xffffffffu, v, o);
        float mu = v * (1.0f/64.0f);
        float d0 = ys[t]-mu, d1 = ys[t+32]-mu;
        float w = d0*d0 + d1*d1;
        #pragma unroll
        for (int o = 16; o > 0; o >>= 1) w += __shfl_xor_sync(0xffffffffu, w, o);
        if (t == 0){ stats[0] = mu; stats[1] = rsqrtf(w*(1.0f/64.0f) + 1e-5f); }
    }
    __syncthreads();
    if (t < DD)
        out[bi*DD + t] = (ys[t]-stats[0])*stats[1]*l2g[t] + l2b[t];
}

extern "C" void kernel_launch(void* const* d_in, const int* in_sizes, int n_in,
                              void* d_out, int out_size){
    const float* q   = (const float*)d_in[0];
    const float* gw1 = (const float*)d_in[1];
    const float* gb1 = (const float*)d_in[2];
    const float* gw2 = (const float*)d_in[3];
    const float* gb2 = (const float*)d_in[4];
    const float* mw1 = (const float*)d_in[5];
    const float* mb1 = (const float*)d_in[6];
    const float* mw2 = (const float*)d_in[7];
    const float* mb2 = (const float*)d_in[8];
    const float* l1g = (const float*)d_in[9];
    const float* l1b = (const float*)d_in[10];
    const float* l2g = (const float*)d_in[11];
    const float* l2b = (const float*)d_in[12];
    float* out = (float*)d_out;

    k_pre<<<BB*SS + 1, 256>>>(q, gw1, gb1, gb2);
    k_w<<<dim3(FF, BB), 128>>>(q, gw2);
    k_main<<<dim3(SS, NFS, BB), 128>>>();
    k_epi<<<BB*SS, 256>>>(q, mw1, mb1, mw2, mb2, l1g, l1b, l2g, l2b, out);
}

// round 7
// speedup vs baseline: 1.1610x; 1.0608x over previous
#include <cuda_runtime.h>
#include <math.h>

// Shapes (fixed by the problem)
#define BB 2
#define SS 128
#define DD 64
#define FF 256
#define DD2 (DD*DD)
#define NFS 2           // f-splits in k_main
#define NG  (NFS*SS)    // 256 split-K groups per batch
#define KC 32           // f-chunk in main kernel
#define WROW 82         // u64 pitch of one k-row in Wd (8-groups at 10-u64 pitch + 2 pad)

typedef unsigned long long u64;

// -------- scratch (device globals: sanctioned, no runtime alloc) --------
__device__ float g_A[BB*SS*FF];              // A[b,i,f]
__device__ float g_C[BB*SS*FF];              // C[b,j,f] (includes gb1)
__device__ float g_W[BB*SS*FF*DD];           // W[b,j,f,e]  16 MB
__device__ float g_Pagg[BB*NG*SS*DD];        // partial agg per group, 16.8 MB
__device__ float g_bias2[BB*DD];             // sum_d gb2[d,e]*Sphi[b,d]

// -------- packed fp32x2 helpers (Blackwell PTX-only FFMA2) --------
__device__ __forceinline__ u64 dup2(float x){
    u64 r; asm("mov.b64 %0, {%1, %1};" : "=l"(r) : "f"(x)); return r;
}
__device__ __forceinline__ u64 fma2(u64 a, u64 b, u64 c){
    u64 d; asm("fma.rn.f32x2 %0, %1, %2, %3;" : "=l"(d) : "l"(a), "l"(b), "l"(c)); return d;
}
__device__ __forceinline__ u64 add2(u64 a, u64 b){
    u64 d; asm("add.rn.f32x2 %0, %1, %2;" : "=l"(d) : "l"(a), "l"(b)); return d;
}
__device__ __forceinline__ float2 unpk(u64 a){
    float2 r; asm("mov.b64 {%0, %1}, %2;" : "=f"(r.x), "=f"(r.y) : "l"(a)); return r;
}
union F4U { float4 f4; ulonglong2 u2; };

__device__ __forceinline__ float gelu_exact(float x){
    return 0.5f * x * (1.0f + erff(x * 0.7071067811865476f));
}

// fast tanh-gelu: 0.5x(1+tanh(0.79788456(x+0.044715x^3))), tanh.approx = 1 MUFU
__device__ __forceinline__ float gelu_fast(float x){
    float x2 = x * x;
    float inner = x * fmaf(0.035677408136f, x2, 0.797884560803f);
    float th;
    asm("tanh.approx.f32 %0, %1;" : "=f"(th) : "f"(inner));
    float hx = 0.5f * x;
    return fmaf(hx, th, hx);
}

// ==================== k_w: W GEMM + (extra blocks) A/C prep + bias2 ====================
// grid (385, 2 b), 128 threads.
//   blocks f in [0,256):   W[b,j,f,e] = sum_d phi[b,j,d]*gw2[f,d*64+e]  (8r x 8e tile)
//   blocks f in [256,384): A/C rows r = (f-256)*2, (f-256)*2+1
//   block  f == 384:       bias2[b,e] = sum_d gb2[d,e]*Sphi[b,d]
__global__ void __launch_bounds__(128) k_w(const float* __restrict__ q,
                                           const float* __restrict__ gw2,
                                           const float* __restrict__ gw1,
                                           const float* __restrict__ gb1,
                                           const float* __restrict__ gb2){
    __shared__ float phiT[DD][SS];              // 32 KB, [d][r]
    __shared__ __align__(16) float g2[DD*DD];   // 16 KB, [d][e]
    __shared__ float ph[2][DD];
    __shared__ float sph[DD];
    int f = blockIdx.x, b = blockIdx.y;
    int t = threadIdx.x;

    if (f < FF){
        // ---- W GEMM role ----
        {
            const float4* src = (const float4*)(gw2 + (size_t)f*DD2);
            float4* dst = (float4*)g2;
            #pragma unroll
            for (int p = 0; p < 8; p++) dst[p*128 + t] = src[p*128 + t];
        }
        {
            const float4* qp = (const float4*)(q + ((size_t)b*SS + t)*DD);
            #pragma unroll
            for (int d4 = 0; d4 < 16; d4++){
                float4 v = qp[d4];
                int d0 = d4*4;
                phiT[d0  ][t] = v.x; phiT[d0+1][t] = v.y;
                phiT[d0+2][t] = v.z; phiT[d0+3][t] = v.w;
            }
        }
        __syncthreads();
        int e0 = (t & 7) * 8;
        int r0 = (t >> 3) * 8;
        u64 acc[8][4];                               // [e][r-pair]
        #pragma unroll
        for (int x = 0; x < 8; x++)
            #pragma unroll
            for (int y = 0; y < 4; y++) acc[x][y] = 0ULL;
        #pragma unroll 4
        for (int d = 0; d < DD; d++){
            F4U p0, p1;
            p0.f4 = *(const float4*)&phiT[d][r0];
            p1.f4 = *(const float4*)&phiT[d][r0 + 4];
            float4 wa = *(const float4*)&g2[d*DD + e0];
            float4 wb = *(const float4*)&g2[d*DD + e0 + 4];
            u64 hp[4] = {p0.u2.x, p0.u2.y, p1.u2.x, p1.u2.y};
            u64 wd8[8] = {dup2(wa.x), dup2(wa.y), dup2(wa.z), dup2(wa.w),
                          dup2(wb.x), dup2(wb.y), dup2(wb.z), dup2(wb.w)};
            #pragma unroll
            for (int e = 0; e < 8; e++)
                #pragma unroll
                for (int ip = 0; ip < 4; ip++)
                    acc[e][ip] = fma2(hp[ip], wd8[e], acc[e][ip]);
        }
        #pragma unroll
        for (int rp = 0; rp < 4; rp++){
            float2 v[8];
            #pragma unroll
            for (int e = 0; e < 8; e++) v[e] = unpk(acc[e][rp]);
            int r = r0 + rp*2;
            float* o0 = &g_W[(((size_t)b*SS + r  )*FF + f)*DD + e0];
            float* o1 = &g_W[(((size_t)b*SS + r+1)*FF + f)*DD + e0];
            *(float4*)(o0    ) = make_float4(v[0].x, v[1].x, v[2].x, v[3].x);
            *(float4*)(o0 + 4) = make_float4(v[4].x, v[5].x, v[6].x, v[7].x);
            *(float4*)(o1    ) = make_float4(v[0].y, v[1].y, v[2].y, v[3].y);
            *(float4*)(o1 + 4) = make_float4(v[4].y, v[5].y, v[6].y, v[7].y);
        }
    } else if (f < FF + SS/2){
        // ---- A/C prep role: 2 rows per block ----
        int r0 = (f - FF) * 2;
        {
            int rr = t >> 6, dd = t & 63;
            ph[rr][dd] = q[((size_t)b*SS + r0 + rr)*DD + dd];
        }
        __syncthreads();
        #pragma unroll
        for (int rr = 0; rr < 2; rr++){
            int bi = b*SS + r0 + rr;
            #pragma unroll
            for (int fo = 0; fo < 2; fo++){
                int ff = t + fo*128;
                float a = 0.f, c = gb1[ff];
                #pragma unroll
                for (int d = 0; d < DD; d++){
                    float p = ph[rr][d];
                    a = fmaf(p, gw1[d*FF + ff], a);
                    c = fmaf(p, gw1[(DD+d)*FF + ff], c);
                }
                g_A[bi*FF + ff] = a;
                g_C[bi*FF + ff] = c;
            }
        }
    } else {
        // ---- bias2 role ----
        if (t < DD){
            float s = 0.f;
            #pragma unroll 8
            for (int j = 0; j < SS; j++) s += q[((size_t)b*SS + j)*DD + t];
            sph[t] = s;
        }
        __syncthreads();
        if (t < DD){
            float ab = 0.f;
            #pragma unroll
            for (int d = 0; d < DD; d++) ab = fmaf(gb2[d*DD + t], sph[d], ab);
            g_bias2[b*DD + t] = ab;
        }
    }
}

// ==================== k_main: split-K GEMM with fused gelu ====================
// grid (128 j, 2 fs, 2 b), 128 threads; thread owns 8 i x 8 e.
// Wd holds the W chunk pre-duplicated (u64), conflict-free padded layout:
//   Wd[k*WROW + (e>>3)*10 + (e&7)]
__global__ void __launch_bounds__(128) k_main(){
    __shared__ __align__(16) float Hs[KC*132];   // H[k][i], padded row 132 (16.9 KB)
    __shared__ __align__(16) u64   Wd[KC*WROW];  // 21 KB
    int j = blockIdx.x, fs = blockIdx.y, b = blockIdx.z;
    int t  = threadIdx.x;
    int m8 = t & 7;                               // e-group: e0 = m8*8
    int i0 = (t >> 3) * 8;
    int kk = t & 31;
    int quar = t >> 5;                            // 0..3
    u64 acc[8][4];                                // [e][i-pair]
    #pragma unroll
    for (int x = 0; x < 8; x++)
        #pragma unroll
        for (int y = 0; y < 4; y++) acc[x][y] = 0ULL;

    const float* Arow = g_A + (size_t)b*SS*FF + fs*(FF/NFS);
    const float* Crow = g_C + ((size_t)b*SS + j)*FF + fs*(FF/NFS);
    const float* Wrow = g_W + ((size_t)b*SS + j)*FF*DD + (size_t)fs*(FF/NFS)*DD;

    int fk = t >> 2;                              // k-row 0..31
    int fe = (t & 3) * 16;                        // e-start

    for (int c = 0; c < (FF/NFS)/KC; c++){        // 4 chunks
        int f0 = c*KC;
        __syncthreads();                          // previous chunk consumed
        // fill W chunk pre-duplicated
        {
            const float4* wsrc = (const float4*)(Wrow + f0*DD);
            #pragma unroll
            for (int qd = 0; qd < 4; qd++){
                float4 w = wsrc[t*4 + qd];
                int e = fe + qd*4;
                int off = fk*WROW + (e>>3)*10 + (e&7);
                ulonglong2 v;
                v.x = dup2(w.x); v.y = dup2(w.y);
                *(ulonglong2*)&Wd[off] = v;
                v.x = dup2(w.z); v.y = dup2(w.w);
                *(ulonglong2*)&Wd[off + 2] = v;
            }
        }
        // fill H chunk: thread owns row kk, 32 i's, vector STS.128 (conflict-free)
        {
            float cv = Crow[f0 + kk];
            #pragma unroll
            for (int m = 0; m < 8; m++){
                int ib = quar*32 + m*4;
                float4 hv;
                hv.x = gelu_fast(Arow[(ib+0)*FF + f0 + kk] + cv);
                hv.y = gelu_fast(Arow[(ib+1)*FF + f0 + kk] + cv);
                hv.z = gelu_fast(Arow[(ib+2)*FF + f0 + kk] + cv);
                hv.w = gelu_fast(Arow[(ib+3)*FF + f0 + kk] + cv);
                *(float4*)&Hs[kk*132 + ib] = hv;
            }
        }
        __syncthreads();
        // FMA loop: 6 LDS.128 + 32 fma2 per k
        #pragma unroll 2
        for (int k = 0; k < KC; k++){
            F4U h0, h1;
            h0.f4 = *(const float4*)&Hs[k*132 + i0];
            h1.f4 = *(const float4*)&Hs[k*132 + i0 + 4];
            const ulonglong2* wp = (const ulonglong2*)&Wd[k*WROW + m8*10];
            ulonglong2 wa = wp[0], wb = wp[1], wc = wp[2], we = wp[3];
            u64 hp[4] = {h0.u2.x, h0.u2.y, h1.u2.x, h1.u2.y};
            u64 wd8[8] = {wa.x, wa.y, wb.x, wb.y, wc.x, wc.y, we.x, we.y};
            #pragma unroll
            for (int e = 0; e < 8; e++)
                #pragma unroll
                for (int ip = 0; ip < 4; ip++)
                    acc[e][ip] = fma2(hp[ip], wd8[e], acc[e][ip]);
        }
    }
    // write partials, group G = fs*SS + j
    int e0 = m8*8;
    float* outp = g_Pagg + (((size_t)b*NG + fs*SS + j)*SS)*DD;
    #pragma unroll
    for (int ip = 0; ip < 4; ip++){
        float2 v[8];
        #pragma unroll
        for (int e = 0; e < 8; e++) v[e] = unpk(acc[e][ip]);
        int ia = i0 + ip*2;
        *(float4*)&outp[(ia  )*DD + e0    ] = make_float4(v[0].x, v[1].x, v[2].x, v[3].x);
        *(float4*)&outp[(ia  )*DD + e0 + 4] = make_float4(v[4].x, v[5].x, v[6].x, v[7].x);
        *(float4*)&outp[(ia+1)*DD + e0    ] = make_float4(v[0].y, v[1].y, v[2].y, v[3].y);
        *(float4*)&outp[(ia+1)*DD + e0 + 4] = make_float4(v[4].y, v[5].y, v[6].y, v[7].y);
    }
}

// ==================== k_epi: wide reduce + LN1 + MLP + LN2 (512 threads) ====================
// grid 256 (b*S rows), 512 threads
__global__ void __launch_bounds__(512) k_epi(const float* __restrict__ q,
                                             const float* __restrict__ mw1,
                                             const float* __restrict__ mb1,
                                             const float* __restrict__ mw2,
                                             const float* __restrict__ mb2,
                                             const float* __restrict__ l1g,
                                             const float* __restrict__ l1b,
                                             const float* __restrict__ l2g,
                                             const float* __restrict__ l2b,
                                             float* __restrict__ out){
    __shared__ float ps2[32][68];                 // reduce partials / fc2 partials
    __shared__ float hp[2][FF];                   // fc1 halves
    __shared__ float xs[DD];
    __shared__ float ys[DD];
    __shared__ float h2[FF];
    __shared__ float stats[2];
    int bi = blockIdx.x;
    int b = bi >> 7, i = bi & 127;
    int t = threadIdx.x;
    // ---- reduce: thread (p in 0..31, slot in 0..15) sums 8 groups x float4 ----
    {
        int slot = t & 15, p = t >> 4;
        int e0 = slot * 4;
        u64 s01 = 0ULL, s23 = 0ULL;
        const float* base = g_Pagg + (((size_t)b*NG + p*8)*SS + i)*DD + e0;
        #pragma unroll
        for (int g = 0; g < 8; g++){
            F4U v; v.f4 = *(const float4*)(base + (size_t)g*SS*DD);
            s01 = add2(s01, v.u2.x);
            s23 = add2(s23, v.u2.y);
        }
        float2 a01 = unpk(s01), a23 = unpk(s23);
        *(float4*)&ps2[p][e0] = make_float4(a01.x, a01.y, a23.x, a23.y);
    }
    __syncthreads();
    if (t < DD){
        float agg = 0.f;
        #pragma unroll
        for (int p = 0; p < 32; p++) agg += ps2[p][t];
        xs[t] = q[bi*DD + t] + agg + g_bias2[b*DD + t];
    }
    __syncthreads();
    // LN1
    if (t < 32){
        float v = xs[t] + xs[t+32];
        #pragma unroll
        for (int o = 16; o > 0; o >>= 1) v += __shfl_xor_sync(0xffffffffu, v, o);
        float mu = v * (1.0f/64.0f);
        float d0 = xs[t]-mu, d1 = xs[t+32]-mu;
        float w = d0*d0 + d1*d1;
        #pragma unroll
        for (int o = 16; o > 0; o >>= 1) w += __shfl_xor_sync(0xffffffffu, w, o);
        if (t == 0){ stats[0] = mu; stats[1] = rsqrtf(w*(1.0f/64.0f) + 1e-5f); }
    }
    __syncthreads();
    if (t < DD) xs[t] = (xs[t]-stats[0])*stats[1]*l1g[t] + l1b[t];
    __syncthreads();
    // fc1 split 2-way over d: thread (half = t>>8, f = t&255)
    {
        int ff = t & 255, half = t >> 8;
        int d0 = half * 32;
        float h = 0.f;
        #pragma unroll
        for (int d = 0; d < 32; d++) h = fmaf(xs[d0 + d], mw1[(d0 + d)*FF + ff], h);
        hp[half][ff] = h;
    }
    __syncthreads();
    if (t < FF) h2[t] = gelu_exact(hp[0][t] + hp[1][t] + mb1[t]);
    __syncthreads();
    // fc2 split 8-way over f: thread (p8 = t>>6, e = t&63)
    {
        int e = t & 63, p8 = t >> 6;
        float o = 0.f;
        #pragma unroll
        for (int f2 = 0; f2 < FF/8; f2++){
            int fi = p8*(FF/8) + f2;
            o = fmaf(h2[fi], mw2[fi*DD + e], o);
        }
        ps2[p8][e] = o;
    }
    __syncthreads();
    if (t < DD){
        float o = 0.f;
        #pragma unroll
        for (int p = 0; p < 8; p++) o += ps2[p][t];
        ys[t] = xs[t] + mb2[t] + o;
    }
    __syncthreads();
    // LN2
    if (t < 32){
        float v = ys[t] + ys[t+32];
        #pragma unroll
        for (int o = 16; o > 0; o >>= 1) v += __shfl_xor_sync(0xffffffffu, v, o);
        float mu = v * (1.0f/64.0f);
        float d0 = ys[t]-mu, d1 = ys[t+32]-mu;
        float w = d0*d0 + d1*d1;
        #pragma unroll
        for (int o = 16; o > 0; o >>= 1) w += __shfl_xor_sync(0xffffffffu, w, o);
        if (t == 0){ stats[0] = mu; stats[1] = rsqrtf(w*(1.0f/64.0f) + 1e-5f); }
    }
    __syncthreads();
    if (t < DD)
        out[bi*DD + t] = (ys[t]-stats[0])*stats[1]*l2g[t] + l2b[t];
}

extern "C" void kernel_launch(void* const* d_in, const int* in_sizes, int n_in,
                              void* d_out, int out_size){
    const float* q   = (const float*)d_in[0];
    const float* gw1 = (const float*)d_in[1];
    const float* gb1 = (const float*)d_in[2];
    const float* gw2 = (const float*)d_in[3];
    const float* gb2 = (const float*)d_in[4];
    const float* mw1 = (const float*)d_in[5];
    const float* mb1 = (const float*)d_in[6];
    const float* mw2 = (const float*)d_in[7];
    const float* mb2 = (const float*)d_in[8];
    const float* l1g = (const float*)d_in[9];
    const float* l1b = (const float*)d_in[10];
    const float* l2g = (const float*)d_in[11];
    const float* l2b = (const float*)d_in[12];
    float* out = (float*)d_out;

    k_w<<<dim3(FF + SS/2 + 1, BB), 128>>>(q, gw2, gw1, gb1, gb2);
    k_main<<<dim3(SS, NFS, BB), 128>>>();
    k_epi<<<BB*SS, 512>>>(q, mw1, mb1, mw2, mb2, l1g, l1b, l2g, l2b, out);
}

// round 8
// speedup vs baseline: 1.1836x; 1.0194x over previous
#include <cuda_runtime.h>
#include <math.h>

// Shapes (fixed by the problem)
#define BB 2
#define SS 128
#define DD 64
#define FF 256
#define DD2 (DD*DD)
#define NFS 2           // f-splits in k_main
#define NG  (NFS*SS)    // 256 split-K groups per batch
#define KC 32           // f-chunk in main kernel
#define WROW 82         // u64 pitch of one k-row in Wd (8-groups at 10-u64 pitch + 2 pad)

typedef unsigned long long u64;

// -------- scratch (device globals: sanctioned, no runtime alloc) --------
__device__ float g_A[BB*SS*FF];              // A[b,i,f]
__device__ float g_C[BB*SS*FF];              // C[b,j,f] (includes gb1)
__device__ float g_W[BB*SS*FF*DD];           // W[b,j,f,e]  16 MB
__device__ float g_Pagg[BB*NG*SS*DD];        // partial agg per group, 16.8 MB
__device__ float g_bias2[BB*DD];             // sum_d gb2[d,e]*Sphi[b,d]

// -------- packed fp32x2 helpers (Blackwell PTX-only FFMA2) --------
__device__ __forceinline__ u64 dup2(float x){
    u64 r; asm("mov.b64 %0, {%1, %1};" : "=l"(r) : "f"(x)); return r;
}
__device__ __forceinline__ u64 fma2(u64 a, u64 b, u64 c){
    u64 d; asm("fma.rn.f32x2 %0, %1, %2, %3;" : "=l"(d) : "l"(a), "l"(b), "l"(c)); return d;
}
__device__ __forceinline__ u64 add2(u64 a, u64 b){
    u64 d; asm("add.rn.f32x2 %0, %1, %2;" : "=l"(d) : "l"(a), "l"(b)); return d;
}
__device__ __forceinline__ float2 unpk(u64 a){
    float2 r; asm("mov.b64 {%0, %1}, %2;" : "=f"(r.x), "=f"(r.y) : "l"(a)); return r;
}
union F4U { float4 f4; ulonglong2 u2; };

__device__ __forceinline__ float gelu_exact(float x){
    return 0.5f * x * (1.0f + erff(x * 0.7071067811865476f));
}

// fast tanh-gelu: 0.5x(1+tanh(0.79788456(x+0.044715x^3))), tanh.approx = 1 MUFU
__device__ __forceinline__ float gelu_fast(float x){
    float x2 = x * x;
    float inner = x * fmaf(0.035677408136f, x2, 0.797884560803f);
    float th;
    asm("tanh.approx.f32 %0, %1;" : "=f"(th) : "f"(inner));
    float hx = 0.5f * x;
    return fmaf(hx, th, hx);
}

// ==================== k_pre: fused prep (A,C) + sphi + bias2 ====================
// grid 257: blocks 0..255 compute A/C row; block 256 computes Sphi + bias2.
__global__ void __launch_bounds__(256) k_pre(const float* __restrict__ q,
                                             const float* __restrict__ gw1,
                                             const float* __restrict__ gb1,
                                             const float* __restrict__ gb2){
    __shared__ float sm[2][DD];
    int bid = blockIdx.x;
    int t = threadIdx.x;
    if (bid < BB*SS){
        int bi = bid, f = t;
        if (f < DD) sm[0][f] = q[bi*DD + f];
        __syncthreads();
        float a = 0.f, c = gb1[f];
        #pragma unroll
        for (int d = 0; d < DD; d++){
            float p = sm[0][d];
            a = fmaf(p, gw1[d*FF + f], a);
            c = fmaf(p, gw1[(DD+d)*FF + f], c);
        }
        g_A[bi*FF + f] = a;
        g_C[bi*FF + f] = c;
    } else {
        if (t < 128){
            int b = t >> 6, d = t & 63;
            float s = 0.f;
            #pragma unroll 8
            for (int j = 0; j < SS; j++) s += q[(b*SS + j)*DD + d];
            sm[b][d] = s;
        }
        __syncthreads();
        if (t < 128){
            int b = t >> 6, e = t & 63;
            float ab = 0.f;
            #pragma unroll
            for (int d = 0; d < DD; d++) ab = fmaf(gb2[d*DD + e], sm[b][d], ab);
            g_bias2[t] = ab;
        }
    }
}

// ==================== k_w: W[b,j,f,e] = sum_d phi[b,j,d]*gw2[f,d*64+e] ====================
// grid (256 f, 2 b), 128 threads; thread owns 8 rows x 8 e (register blocked).
// launch_bounds(128,4) caps regs at 128 -> 4 CTAs/SM.
__global__ void __launch_bounds__(128, 4) k_w(const float* __restrict__ q,
                                              const float* __restrict__ gw2){
    __shared__ float phiT[DD][SS];              // 32 KB, [d][r]
    __shared__ __align__(16) float g2[DD*DD];   // 16 KB, [d][e]
    int f = blockIdx.x, b = blockIdx.y;
    int t = threadIdx.x;
    {
        const float4* src = (const float4*)(gw2 + (size_t)f*DD2);
        float4* dst = (float4*)g2;
        #pragma unroll
        for (int p = 0; p < 8; p++) dst[p*128 + t] = src[p*128 + t];
    }
    {
        const float4* qp = (const float4*)(q + ((size_t)b*SS + t)*DD);
        #pragma unroll
        for (int d4 = 0; d4 < 16; d4++){
            float4 v = qp[d4];
            int d0 = d4*4;
            phiT[d0  ][t] = v.x; phiT[d0+1][t] = v.y;
            phiT[d0+2][t] = v.z; phiT[d0+3][t] = v.w;
        }
    }
    __syncthreads();
    int e0 = (t & 7) * 8;
    int r0 = (t >> 3) * 8;
    u64 acc[8][4];                               // [e][r-pair]
    #pragma unroll
    for (int x = 0; x < 8; x++)
        #pragma unroll
        for (int y = 0; y < 4; y++) acc[x][y] = 0ULL;
    #pragma unroll 4
    for (int d = 0; d < DD; d++){
        F4U p0, p1;
        p0.f4 = *(const float4*)&phiT[d][r0];
        p1.f4 = *(const float4*)&phiT[d][r0 + 4];
        float4 wa = *(const float4*)&g2[d*DD + e0];
        float4 wb = *(const float4*)&g2[d*DD + e0 + 4];
        u64 hp[4] = {p0.u2.x, p0.u2.y, p1.u2.x, p1.u2.y};
        u64 wd8[8] = {dup2(wa.x), dup2(wa.y), dup2(wa.z), dup2(wa.w),
                      dup2(wb.x), dup2(wb.y), dup2(wb.z), dup2(wb.w)};
        #pragma unroll
        for (int e = 0; e < 8; e++)
            #pragma unroll
            for (int ip = 0; ip < 4; ip++)
                acc[e][ip] = fma2(hp[ip], wd8[e], acc[e][ip]);
    }
    #pragma unroll
    for (int rp = 0; rp < 4; rp++){
        float2 v[8];
        #pragma unroll
        for (int e = 0; e < 8; e++) v[e] = unpk(acc[e][rp]);
        int r = r0 + rp*2;
        float* o0 = &g_W[(((size_t)b*SS + r  )*FF + f)*DD + e0];
        float* o1 = &g_W[(((size_t)b*SS + r+1)*FF + f)*DD + e0];
        *(float4*)(o0    ) = make_float4(v[0].x, v[1].x, v[2].x, v[3].x);
        *(float4*)(o0 + 4) = make_float4(v[4].x, v[5].x, v[6].x, v[7].x);
        *(float4*)(o1    ) = make_float4(v[0].y, v[1].y, v[2].y, v[3].y);
        *(float4*)(o1 + 4) = make_float4(v[4].y, v[5].y, v[6].y, v[7].y);
    }
}

// ==================== k_main: split-K GEMM with fused gelu ====================
// grid (128 j, 2 fs, 2 b), 128 threads; thread owns 8 i x 8 e.
// Wd holds the W chunk pre-duplicated (u64), conflict-free padded layout:
//   Wd[k*WROW + (e>>3)*10 + (e&7)]
__global__ void __launch_bounds__(128, 4) k_main(){
    __shared__ __align__(16) float Hs[KC*132];   // H[k][i], padded row 132 (16.9 KB)
    __shared__ __align__(16) u64   Wd[KC*WROW];  // 21 KB
    int j = blockIdx.x, fs = blockIdx.y, b = blockIdx.z;
    int t  = threadIdx.x;
    int m8 = t & 7;                               // e-group: e0 = m8*8
    int i0 = (t >> 3) * 8;
    int kk = t & 31;
    int quar = t >> 5;                            // 0..3
    u64 acc[8][4];                                // [e][i-pair]
    #pragma unroll
    for (int x = 0; x < 8; x++)
        #pragma unroll
        for (int y = 0; y < 4; y++) acc[x][y] = 0ULL;

    const float* Arow = g_A + (size_t)b*SS*FF + fs*(FF/NFS);
    const float* Crow = g_C + ((size_t)b*SS + j)*FF + fs*(FF/NFS);
    const float* Wrow = g_W + ((size_t)b*SS + j)*FF*DD + (size_t)fs*(FF/NFS)*DD;

    int fk = t >> 2;                              // k-row 0..31
    int fe = (t & 3) * 16;                        // e-start

    for (int c = 0; c < (FF/NFS)/KC; c++){        // 4 chunks
        int f0 = c*KC;
        __syncthreads();                          // previous chunk consumed
        // fill W chunk pre-duplicated
        {
            const float4* wsrc = (const float4*)(Wrow + f0*DD);
            #pragma unroll
            for (int qd = 0; qd < 4; qd++){
                float4 w = wsrc[t*4 + qd];
                int e = fe + qd*4;
                int off = fk*WROW + (e>>3)*10 + (e&7);
                ulonglong2 v;
                v.x = dup2(w.x); v.y = dup2(w.y);
                *(ulonglong2*)&Wd[off] = v;
                v.x = dup2(w.z); v.y = dup2(w.w);
                *(ulonglong2*)&Wd[off + 2] = v;
            }
        }
        // fill H chunk: thread owns row kk, 32 i's, vector STS.128 (conflict-free)
        {
            float cv = Crow[f0 + kk];
            #pragma unroll
            for (int m = 0; m < 8; m++){
                int ib = quar*32 + m*4;
                float4 hv;
                hv.x = gelu_fast(Arow[(ib+0)*FF + f0 + kk] + cv);
                hv.y = gelu_fast(Arow[(ib+1)*FF + f0 + kk] + cv);
                hv.z = gelu_fast(Arow[(ib+2)*FF + f0 + kk] + cv);
                hv.w = gelu_fast(Arow[(ib+3)*FF + f0 + kk] + cv);
                *(float4*)&Hs[kk*132 + ib] = hv;
            }
        }
        __syncthreads();
        // FMA loop: 6 LDS.128 + 32 fma2 per k
        #pragma unroll 2
        for (int k = 0; k < KC; k++){
            F4U h0, h1;
            h0.f4 = *(const float4*)&Hs[k*132 + i0];
            h1.f4 = *(const float4*)&Hs[k*132 + i0 + 4];
            const ulonglong2* wp = (const ulonglong2*)&Wd[k*WROW + m8*10];
            ulonglong2 wa = wp[0], wb = wp[1], wc = wp[2], we = wp[3];
            u64 hp[4] = {h0.u2.x, h0.u2.y, h1.u2.x, h1.u2.y};
            u64 wd8[8] = {wa.x, wa.y, wb.x, wb.y, wc.x, wc.y, we.x, we.y};
            #pragma unroll
            for (int e = 0; e < 8; e++)
                #pragma unroll
                for (int ip = 0; ip < 4; ip++)
                    acc[e][ip] = fma2(hp[ip], wd8[e], acc[e][ip]);
        }
    }
    // write partials, group G = fs*SS + j
    int e0 = m8*8;
    float* outp = g_Pagg + (((size_t)b*NG + fs*SS + j)*SS)*DD;
    #pragma unroll
    for (int ip = 0; ip < 4; ip++){
        float2 v[8];
        #pragma unroll
        for (int e = 0; e < 8; e++) v[e] = unpk(acc[e][ip]);
        int ia = i0 + ip*2;
        *(float4*)&outp[(ia  )*DD + e0    ] = make_float4(v[0].x, v[1].x, v[2].x, v[3].x);
        *(float4*)&outp[(ia  )*DD + e0 + 4] = make_float4(v[4].x, v[5].x, v[6].x, v[7].x);
        *(float4*)&outp[(ia+1)*DD + e0    ] = make_float4(v[0].y, v[1].y, v[2].y, v[3].y);
        *(float4*)&outp[(ia+1)*DD + e0 + 4] = make_float4(v[4].y, v[5].y, v[6].y, v[7].y);
    }
}

// ==================== k_epi: wide reduce + LN1 + MLP + LN2 (512 threads) ====================
// grid 256 (b*S rows), 512 threads
__global__ void __launch_bounds__(512) k_epi(const float* __restrict__ q,
                                             const float* __restrict__ mw1,
                                             const float* __restrict__ mb1,
                                             const float* __restrict__ mw2,
                                             const float* __restrict__ mb2,
                                             const float* __restrict__ l1g,
                                             const float* __restrict__ l1b,
                                             const float* __restrict__ l2g,
                                             const float* __restrict__ l2b,
                                             float* __restrict__ out){
    __shared__ float ps2[32][68];                 // reduce partials / fc2 partials
    __shared__ float hp[2][FF];                   // fc1 halves
    __shared__ float xs[DD];
    __shared__ float ys[DD];
    __shared__ float h2[FF];
    __shared__ float stats[2];
    int bi = blockIdx.x;
    int b = bi >> 7, i = bi & 127;
    int t = threadIdx.x;
    // ---- reduce: thread (p in 0..31, slot in 0..15) sums 8 groups x float4 ----
    {
        int slot = t & 15, p = t >> 4;
        int e0 = slot * 4;
        u64 s01 = 0ULL, s23 = 0ULL;
        const float* base = g_Pagg + (((size_t)b*NG + p*8)*SS + i)*DD + e0;
        #pragma unroll
        for (int g = 0; g < 8; g++){
            F4U v; v.f4 = *(const float4*)(base + (size_t)g*SS*DD);
            s01 = add2(s01, v.u2.x);
            s23 = add2(s23, v.u2.y);
        }
        float2 a01 = unpk(s01), a23 = unpk(s23);
        *(float4*)&ps2[p][e0] = make_float4(a01.x, a01.y, a23.x, a23.y);
    }
    __syncthreads();
    if (t < DD){
        float agg = 0.f;
        #pragma unroll
        for (int p = 0; p < 32; p++) agg += ps2[p][t];
        xs[t] = q[bi*DD + t] + agg + g_bias2[b*DD + t];
    }
    __syncthreads();
    // LN1
    if (t < 32){
        float v = xs[t] + xs[t+32];
        #pragma unroll
        for (int o = 16; o > 0; o >>= 1) v += __shfl_xor_sync(0xffffffffu, v, o);
        float mu = v * (1.0f/64.0f);
        float d0 = xs[t]-mu, d1 = xs[t+32]-mu;
        float w = d0*d0 + d1*d1;
        #pragma unroll
        for (int o = 16; o > 0; o >>= 1) w += __shfl_xor_sync(0xffffffffu, w, o);
        if (t == 0){ stats[0] = mu; stats[1] = rsqrtf(w*(1.0f/64.0f) + 1e-5f); }
    }
    __syncthreads();
    if (t < DD) xs[t] = (xs[t]-stats[0])*stats[1]*l1g[t] + l1b[t];
    __syncthreads();
    // fc1 split 2-way over d: thread (half = t>>8, f = t&255)
    {
        int ff = t & 255, half = t >> 8;
        int d0 = half * 32;
        float h = 0.f;
        #pragma unroll
        for (int d = 0; d < 32; d++) h = fmaf(xs[d0 + d], mw1[(d0 + d)*FF + ff], h);
        hp[half][ff] = h;
    }
    __syncthreads();
    if (t < FF) h2[t] = gelu_exact(hp[0][t] + hp[1][t] + mb1[t]);
    __syncthreads();
    // fc2 split 8-way over f: thread (p8 = t>>6, e = t&63)
    {
        int e = t & 63, p8 = t >> 6;
        float o = 0.f;
        #pragma unroll
        for (int f2 = 0; f2 < FF/8; f2++){
            int fi = p8*(FF/8) + f2;
            o = fmaf(h2[fi], mw2[fi*DD + e], o);
        }
        ps2[p8][e] = o;
    }
    __syncthreads();
    if (t < DD){
        float o = 0.f;
        #pragma unroll
        for (int p = 0; p < 8; p++) o += ps2[p][t];
        ys[t] = xs[t] + mb2[t] + o;
    }
    __syncthreads();
    // LN2
    if (t < 32){
        float v = ys[t] + ys[t+32];
        #pragma unroll
        for (int o = 16; o > 0; o >>= 1) v += __shfl_xor_sync(0xffffffffu, v, o);
        float mu = v * (1.0f/64.0f);
        float d0 = ys[t]-mu, d1 = ys[t+32]-mu;
        float w = d0*d0 + d1*d1;
        #pragma unroll
        for (int o = 16; o > 0; o >>= 1) w += __shfl_xor_sync(0xffffffffu, w, o);
        if (t == 0){ stats[0] = mu; stats[1] = rsqrtf(w*(1.0f/64.0f) + 1e-5f); }
    }
    __syncthreads();
    if (t < DD)
        out[bi*DD + t] = (ys[t]-stats[0])*stats[1]*l2g[t] + l2b[t];
}

extern "C" void kernel_launch(void* const* d_in, const int* in_sizes, int n_in,
                              void* d_out, int out_size){
    const float* q   = (const float*)d_in[0];
    const float* gw1 = (const float*)d_in[1];
    const float* gb1 = (const float*)d_in[2];
    const float* gw2 = (const float*)d_in[3];
    const float* gb2 = (const float*)d_in[4];
    const float* mw1 = (const float*)d_in[5];
    const float* mb1 = (const float*)d_in[6];
    const float* mw2 = (const float*)d_in[7];
    const float* mb2 = (const float*)d_in[8];
    const float* l1g = (const float*)d_in[9];
    const float* l1b = (const float*)d_in[10];
    const float* l2g = (const float*)d_in[11];
    const float* l2b = (const float*)d_in[12];
    float* out = (float*)d_out;

    k_pre<<<BB*SS + 1, 256>>>(q, gw1, gb1, gb2);
    k_w<<<dim3(FF, BB), 128>>>(q, gw2);
    k_main<<<dim3(SS, NFS, BB), 128>>>();
    k_epi<<<BB*SS, 512>>>(q, mw1, mb1, mw2, mb2, l1g, l1b, l2g, l2b, out);
}

// round 9
// speedup vs baseline: 1.2624x; 1.0666x over previous
#include <cuda_runtime.h>
#include <math.h>

// Shapes (fixed by the problem)
#define BB 2
#define SS 128
#define DD 64
#define FF 256
#define DD2 (DD*DD)
#define NFS 2           // f-splits in k_main
#define NG  (NFS*SS)    // 256 split-K groups per batch
#define KC 32           // f-chunk in main kernel
#define WROW 82         // u64 pitch of one k-row in Wd (8-groups at 10-u64 pitch + 2 pad)

typedef unsigned long long u64;

// -------- scratch (device globals: sanctioned, no runtime alloc) --------
__device__ float g_A[BB*SS*FF];              // A[b,i,f]
__device__ float g_C[BB*SS*FF];              // C[b,j,f] (includes gb1)
__device__ float g_W[BB*SS*FF*DD];           // W[b,j,f,e]  16 MB
__device__ float g_Pagg[BB*NG*SS*DD];        // partial agg per group, 16.8 MB
__device__ float g_bias2[BB*DD];             // sum_d gb2[d,e]*Sphi[b,d]

// -------- packed fp32x2 helpers (Blackwell PTX-only FFMA2) --------
__device__ __forceinline__ u64 dup2(float x){
    u64 r; asm("mov.b64 %0, {%1, %1};" : "=l"(r) : "f"(x)); return r;
}
__device__ __forceinline__ u64 fma2(u64 a, u64 b, u64 c){
    u64 d; asm("fma.rn.f32x2 %0, %1, %2, %3;" : "=l"(d) : "l"(a), "l"(b), "l"(c)); return d;
}
__device__ __forceinline__ u64 add2(u64 a, u64 b){
    u64 d; asm("add.rn.f32x2 %0, %1, %2;" : "=l"(d) : "l"(a), "l"(b)); return d;
}
__device__ __forceinline__ float2 unpk(u64 a){
    float2 r; asm("mov.b64 {%0, %1}, %2;" : "=f"(r.x), "=f"(r.y) : "l"(a)); return r;
}
union F4U { float4 f4; ulonglong2 u2; };

__device__ __forceinline__ float gelu_exact(float x){
    return 0.5f * x * (1.0f + erff(x * 0.7071067811865476f));
}

// fast tanh-gelu: 0.5x(1+tanh(0.79788456(x+0.044715x^3))), tanh.approx = 1 MUFU
__device__ __forceinline__ float gelu_fast(float x){
    float x2 = x * x;
    float inner = x * fmaf(0.035677408136f, x2, 0.797884560803f);
    float th;
    asm("tanh.approx.f32 %0, %1;" : "=f"(th) : "f"(inner));
    float hx = 0.5f * x;
    return fmaf(hx, th, hx);
}

// ==================== k_w: W GEMM + (extra blocks) A/C prep + bias2 ====================
// grid (321, 2 b), 128 threads, reg-capped (128,4).
//   blocks f in [0,256):   W[b,j,f,e] (8r x 8e register tile)
//   blocks f in [256,320): A/C rows r = (f-256)*2, (f-256)*2+1
//   block  f == 320:       bias2[b,e]
__global__ void __launch_bounds__(128, 4) k_w(const float* __restrict__ q,
                                              const float* __restrict__ gw2,
                                              const float* __restrict__ gw1,
                                              const float* __restrict__ gb1,
                                              const float* __restrict__ gb2){
    __shared__ float phiT[DD][SS];              // 32 KB, [d][r]
    __shared__ __align__(16) float g2[DD*DD];   // 16 KB, [d][e]
    __shared__ float ph[2][DD];
    __shared__ float sph[DD];
    int f = blockIdx.x, b = blockIdx.y;
    int t = threadIdx.x;

    if (f < FF){
        // ---- W GEMM role ----
        {
            const float4* src = (const float4*)(gw2 + (size_t)f*DD2);
            float4* dst = (float4*)g2;
            #pragma unroll
            for (int p = 0; p < 8; p++) dst[p*128 + t] = src[p*128 + t];
        }
        {
            const float4* qp = (const float4*)(q + ((size_t)b*SS + t)*DD);
            #pragma unroll
            for (int d4 = 0; d4 < 16; d4++){
                float4 v = qp[d4];
                int d0 = d4*4;
                phiT[d0  ][t] = v.x; phiT[d0+1][t] = v.y;
                phiT[d0+2][t] = v.z; phiT[d0+3][t] = v.w;
            }
        }
        __syncthreads();
        int e0 = (t & 7) * 8;
        int r0 = (t >> 3) * 8;
        u64 acc[8][4];                               // [e][r-pair]
        #pragma unroll
        for (int x = 0; x < 8; x++)
            #pragma unroll
            for (int y = 0; y < 4; y++) acc[x][y] = 0ULL;
        #pragma unroll 4
        for (int d = 0; d < DD; d++){
            F4U p0, p1;
            p0.f4 = *(const float4*)&phiT[d][r0];
            p1.f4 = *(const float4*)&phiT[d][r0 + 4];
            float4 wa = *(const float4*)&g2[d*DD + e0];
            float4 wb = *(const float4*)&g2[d*DD + e0 + 4];
            u64 hp[4] = {p0.u2.x, p0.u2.y, p1.u2.x, p1.u2.y};
            u64 wd8[8] = {dup2(wa.x), dup2(wa.y), dup2(wa.z), dup2(wa.w),
                          dup2(wb.x), dup2(wb.y), dup2(wb.z), dup2(wb.w)};
            #pragma unroll
            for (int e = 0; e < 8; e++)
                #pragma unroll
                for (int ip = 0; ip < 4; ip++)
                    acc[e][ip] = fma2(hp[ip], wd8[e], acc[e][ip]);
        }
        #pragma unroll
        for (int rp = 0; rp < 4; rp++){
            float2 v[8];
            #pragma unroll
            for (int e = 0; e < 8; e++) v[e] = unpk(acc[e][rp]);
            int r = r0 + rp*2;
            float* o0 = &g_W[(((size_t)b*SS + r  )*FF + f)*DD + e0];
            float* o1 = &g_W[(((size_t)b*SS + r+1)*FF + f)*DD + e0];
            *(float4*)(o0    ) = make_float4(v[0].x, v[1].x, v[2].x, v[3].x);
            *(float4*)(o0 + 4) = make_float4(v[4].x, v[5].x, v[6].x, v[7].x);
            *(float4*)(o1    ) = make_float4(v[0].y, v[1].y, v[2].y, v[3].y);
            *(float4*)(o1 + 4) = make_float4(v[4].y, v[5].y, v[6].y, v[7].y);
        }
    } else if (f < FF + SS/2){
        // ---- A/C prep role: 2 rows per block ----
        int r0 = (f - FF) * 2;
        {
            int rr = t >> 6, dd = t & 63;
            ph[rr][dd] = q[((size_t)b*SS + r0 + rr)*DD + dd];
        }
        __syncthreads();
        #pragma unroll
        for (int rr = 0; rr < 2; rr++){
            int bi = b*SS + r0 + rr;
            #pragma unroll
            for (int fo = 0; fo < 2; fo++){
                int ff = t + fo*128;
                float a = 0.f, c = gb1[ff];
                #pragma unroll
                for (int d = 0; d < DD; d++){
                    float p = ph[rr][d];
                    a = fmaf(p, gw1[d*FF + ff], a);
                    c = fmaf(p, gw1[(DD+d)*FF + ff], c);
                }
                g_A[bi*FF + ff] = a;
                g_C[bi*FF + ff] = c;
            }
        }
    } else {
        // ---- bias2 role ----
        if (t < DD){
            float s = 0.f;
            #pragma unroll 8
            for (int j = 0; j < SS; j++) s += q[((size_t)b*SS + j)*DD + t];
            sph[t] = s;
        }
        __syncthreads();
        if (t < DD){
            float ab = 0.f;
            #pragma unroll
            for (int d = 0; d < DD; d++) ab = fmaf(gb2[d*DD + t], sph[d], ab);
            g_bias2[b*DD + t] = ab;
        }
    }
}

// ==================== k_main: split-K GEMM with fused gelu ====================
// grid (128 j, 2 fs, 2 b), 128 threads; thread owns 8 i x 8 e.
// Wd holds the W chunk pre-duplicated (u64), conflict-free padded layout:
//   Wd[k*WROW + (e>>3)*10 + (e&7)]
__global__ void __launch_bounds__(128, 4) k_main(){
    __shared__ __align__(16) float Hs[KC*132];   // H[k][i], padded row 132 (16.9 KB)
    __shared__ __align__(16) u64   Wd[KC*WROW];  // 21 KB
    int j = blockIdx.x, fs = blockIdx.y, b = blockIdx.z;
    int t  = threadIdx.x;
    int m8 = t & 7;                               // e-group: e0 = m8*8
    int i0 = (t >> 3) * 8;
    int kk = t & 31;
    int quar = t >> 5;                            // 0..3
    u64 acc[8][4];                                // [e][i-pair]
    #pragma unroll
    for (int x = 0; x < 8; x++)
        #pragma unroll
        for (int y = 0; y < 4; y++) acc[x][y] = 0ULL;

    const float* Arow = g_A + (size_t)b*SS*FF + fs*(FF/NFS);
    const float* Crow = g_C + ((size_t)b*SS + j)*FF + fs*(FF/NFS);
    const float* Wrow = g_W + ((size_t)b*SS + j)*FF*DD + (size_t)fs*(FF/NFS)*DD;

    int fk = t >> 2;                              // k-row 0..31
    int fe = (t & 3) * 16;                        // e-start

    for (int c = 0; c < (FF/NFS)/KC; c++){        // 4 chunks
        int f0 = c*KC;
        __syncthreads();                          // previous chunk consumed
        // fill W chunk pre-duplicated
        {
            const float4* wsrc = (const float4*)(Wrow + f0*DD);
            #pragma unroll
            for (int qd = 0; qd < 4; qd++){
                float4 w = wsrc[t*4 + qd];
                int e = fe + qd*4;
                int off = fk*WROW + (e>>3)*10 + (e&7);
                ulonglong2 v;
                v.x = dup2(w.x); v.y = dup2(w.y);
                *(ulonglong2*)&Wd[off] = v;
                v.x = dup2(w.z); v.y = dup2(w.w);
                *(ulonglong2*)&Wd[off + 2] = v;
            }
        }
        // fill H chunk: thread owns row kk, 32 i's, vector STS.128 (conflict-free)
        {
            float cv = Crow[f0 + kk];
            #pragma unroll
            for (int m = 0; m < 8; m++){
                int ib = quar*32 + m*4;
                float4 hv;
                hv.x = gelu_fast(Arow[(ib+0)*FF + f0 + kk] + cv);
                hv.y = gelu_fast(Arow[(ib+1)*FF + f0 + kk] + cv);
                hv.z = gelu_fast(Arow[(ib+2)*FF + f0 + kk] + cv);
                hv.w = gelu_fast(Arow[(ib+3)*FF + f0 + kk] + cv);
                *(float4*)&Hs[kk*132 + ib] = hv;
            }
        }
        __syncthreads();
        // FMA loop: 6 LDS.128 + 32 fma2 per k
        #pragma unroll 2
        for (int k = 0; k < KC; k++){
            F4U h0, h1;
            h0.f4 = *(const float4*)&Hs[k*132 + i0];
            h1.f4 = *(const float4*)&Hs[k*132 + i0 + 4];
            const ulonglong2* wp = (const ulonglong2*)&Wd[k*WROW + m8*10];
            ulonglong2 wa = wp[0], wb = wp[1], wc = wp[2], we = wp[3];
            u64 hp[4] = {h0.u2.x, h0.u2.y, h1.u2.x, h1.u2.y};
            u64 wd8[8] = {wa.x, wa.y, wb.x, wb.y, wc.x, wc.y, we.x, we.y};
            #pragma unroll
            for (int e = 0; e < 8; e++)
                #pragma unroll
                for (int ip = 0; ip < 4; ip++)
                    acc[e][ip] = fma2(hp[ip], wd8[e], acc[e][ip]);
        }
    }
    // write partials, group G = fs*SS + j
    int e0 = m8*8;
    float* outp = g_Pagg + (((size_t)b*NG + fs*SS + j)*SS)*DD;
    #pragma unroll
    for (int ip = 0; ip < 4; ip++){
        float2 v[8];
        #pragma unroll
        for (int e = 0; e < 8; e++) v[e] = unpk(acc[e][ip]);
        int ia = i0 + ip*2;
        *(float4*)&outp[(ia  )*DD + e0    ] = make_float4(v[0].x, v[1].x, v[2].x, v[3].x);
        *(float4*)&outp[(ia  )*DD + e0 + 4] = make_float4(v[4].x, v[5].x, v[6].x, v[7].x);
        *(float4*)&outp[(ia+1)*DD + e0    ] = make_float4(v[0].y, v[1].y, v[2].y, v[3].y);
        *(float4*)&outp[(ia+1)*DD + e0 + 4] = make_float4(v[4].y, v[5].y, v[6].y, v[7].y);
    }
}

// ==================== k_epi: MLP-8 reduce + LN1 + MLP + LN2 (512 threads) ====================
// grid 256 (b*S rows), 512 threads
__global__ void __launch_bounds__(512) k_epi(const float* __restrict__ q,
                                             const float* __restrict__ mw1,
                                             const float* __restrict__ mb1,
                                             const float* __restrict__ mw2,
                                             const float* __restrict__ mb2,
                                             const float* __restrict__ l1g,
                                             const float* __restrict__ l1b,
                                             const float* __restrict__ l2g,
                                             const float* __restrict__ l2b,
                                             float* __restrict__ out){
    __shared__ float ps2[32][68];                 // reduce partials / fc2 partials
    __shared__ float hp[2][FF];                   // fc1 halves
    __shared__ float xs[DD];
    __shared__ float ys[DD];
    __shared__ float h2[FF];
    __shared__ float stats[2];
    int bi = blockIdx.x;
    int b = bi >> 7, i = bi & 127;
    int t = threadIdx.x;
    // ---- reduce: thread (p in 0..31, slot in 0..15): load 8 groups x float4
    //      into a register array FIRST (MLP=8), then fixed pairwise add tree ----
    {
        int slot = t & 15, p = t >> 4;
        int e0 = slot * 4;
        const float* base = g_Pagg + (((size_t)b*NG + p*8)*SS + i)*DD + e0;
        F4U v[8];
        #pragma unroll
        for (int g = 0; g < 8; g++)
            v[g].f4 = *(const float4*)(base + (size_t)g*SS*DD);
        u64 s01 = add2(add2(add2(v[0].u2.x, v[1].u2.x), add2(v[2].u2.x, v[3].u2.x)),
                       add2(add2(v[4].u2.x, v[5].u2.x), add2(v[6].u2.x, v[7].u2.x)));
        u64 s23 = add2(add2(add2(v[0].u2.y, v[1].u2.y), add2(v[2].u2.y, v[3].u2.y)),
                       add2(add2(v[4].u2.y, v[5].u2.y), add2(v[6].u2.y, v[7].u2.y)));
        float2 a01 = unpk(s01), a23 = unpk(s23);
        *(float4*)&ps2[p][e0] = make_float4(a01.x, a01.y, a23.x, a23.y);
    }
    __syncthreads();
    if (t < DD){
        float agg = 0.f;
        #pragma unroll
        for (int p = 0; p < 32; p++) agg += ps2[p][t];
        xs[t] = q[bi*DD + t] + agg + g_bias2[b*DD + t];
    }
    __syncthreads();
    // LN1
    if (t < 32){
        float v = xs[t] + xs[t+32];
        #pragma unroll
        for (int o = 16; o > 0; o >>= 1) v += __shfl_xor_sync(0xffffffffu, v, o);
        float mu = v * (1.0f/64.0f);
        float d0 = xs[t]-mu, d1 = xs[t+32]-mu;
        float w = d0*d0 + d1*d1;
        #pragma unroll
        for (int o = 16; o > 0; o >>= 1) w += __shfl_xor_sync(0xffffffffu, w, o);
        if (t == 0){ stats[0] = mu; stats[1] = rsqrtf(w*(1.0f/64.0f) + 1e-5f); }
    }
    __syncthreads();
    if (t < DD) xs[t] = (xs[t]-stats[0])*stats[1]*l1g[t] + l1b[t];
    __syncthreads();
    // fc1 split 2-way over d: thread (half = t>>8, f = t&255)
    {
        int ff = t & 255, half = t >> 8;
        int d0 = half * 32;
        float h = 0.f;
        #pragma unroll
        for (int d = 0; d < 32; d++) h = fmaf(xs[d0 + d], mw1[(d0 + d)*FF + ff], h);
        hp[half][ff] = h;
    }
    __syncthreads();
    if (t < FF) h2[t] = gelu_exact(hp[0][t] + hp[1][t] + mb1[t]);
    __syncthreads();
    // fc2 split 8-way over f: thread (p8 = t>>6, e = t&63)
    {
        int e = t & 63, p8 = t >> 6;
        float o = 0.f;
        #pragma unroll
        for (int f2 = 0; f2 < FF/8; f2++){
            int fi = p8*(FF/8) + f2;
            o = fmaf(h2[fi], mw2[fi*DD + e], o);
        }
        ps2[p8][e] = o;
    }
    __syncthreads();
    if (t < DD){
        float o = 0.f;
        #pragma unroll
        for (int p = 0; p < 8; p++) o += ps2[p][t];
        ys[t] = xs[t] + mb2[t] + o;
    }
    __syncthreads();
    // LN2
    if (t < 32){
        float v = ys[t] + ys[t+32];
        #pragma unroll
        for (int o = 16; o > 0; o >>= 1) v += __shfl_xor_sync(0xffffffffu, v, o);
        float mu = v * (1.0f/64.0f);
        float d0 = ys[t]-mu, d1 = ys[t+32]-mu;
        float w = d0*d0 + d1*d1;
        #pragma unroll
        for (int o = 16; o > 0; o >>= 1) w += __shfl_xor_sync(0xffffffffu, w, o);
        if (t == 0){ stats[0] = mu; stats[1] = rsqrtf(w*(1.0f/64.0f) + 1e-5f); }
    }
    __syncthreads();
    if (t < DD)
        out[bi*DD + t] = (ys[t]-stats[0])*stats[1]*l2g[t] + l2b[t];
}

extern "C" void kernel_launch(void* const* d_in, const int* in_sizes, int n_in,
                              void* d_out, int out_size){
    const float* q   = (const float*)d_in[0];
    const float* gw1 = (const float*)d_in[1];
    const float* gb1 = (const float*)d_in[2];
    const float* gw2 = (const float*)d_in[3];
    const float* gb2 = (const float*)d_in[4];
    const float* mw1 = (const float*)d_in[5];
    const float* mb1 = (const float*)d_in[6];
    const float* mw2 = (const float*)d_in[7];
    const float* mb2 = (const float*)d_in[8];
    const float* l1g = (const float*)d_in[9];
    const float* l1b = (const float*)d_in[10];
    const float* l2g = (const float*)d_in[11];
    const float* l2b = (const float*)d_in[12];
    float* out = (float*)d_out;

    k_w<<<dim3(FF + SS/2 + 1, BB), 128>>>(q, gw2, gw1, gb1, gb2);
    k_main<<<dim3(SS, NFS, BB), 128>>>();
    k_epi<<<BB*SS, 512>>>(q, mw1, mb1, mw2, mb2, l1g, l1b, l2g, l2b, out);
}